// round 1
// baseline (speedup 1.0000x reference)
#include <cuda_runtime.h>
#include <cuda_bf16.h>

#define BSZ 8
#define LEN 2048
#define HID 1024
#define NH  16
#define HD  64
#define MTOT (BSZ*LEN)      /* 16384 */
#define NKV  (NH*HD)        /* 1024  */

// Scratch (device globals: allocation-free rule)
__device__ float g_V1[(size_t)MTOT * NKV];
__device__ float g_K1[(size_t)MTOT * NKV];
__device__ unsigned char g_valid[MTOT * NH];
__device__ int2 g_fm[MTOT * NH];
__device__ int2 g_bm[MTOT * NH];

// ---------------------------------------------------------------------------
// SGEMM: C = relu(A @ W + bias), A [MTOT, HID] row-major, W [HID, NKV] row-major
// 128x128 tile, BK=8, 256 threads, 8x8 per thread, double-buffered smem.
// grid.x in [0,16): 0..7 -> V columns, 8..15 -> K columns.
// ---------------------------------------------------------------------------
#define BM 128
#define BN 128
#define BK 8

__global__ __launch_bounds__(256, 2)
void gemm_relu_kernel(const float* __restrict__ A,
                      const float* __restrict__ Wv, const float* __restrict__ Bv,
                      const float* __restrict__ Wk, const float* __restrict__ Bk)
{
    __shared__ float As[2][BK][BM];
    __shared__ float Bs[2][BK][BN];

    const bool isK = (blockIdx.x >= 8);
    const float* __restrict__ W    = isK ? Wk : Wv;
    const float* __restrict__ bias = isK ? Bk : Bv;
    float* __restrict__ Cout       = isK ? g_K1 : g_V1;

    const int n0 = (blockIdx.x & 7) * BN;
    const int m0 = blockIdx.y * BM;
    const int tid = threadIdx.x;
    const int tx = tid & 15, ty = tid >> 4;

    const int arow = tid >> 1;          // 0..127
    const int acol = (tid & 1) * 4;     // 0 or 4
    const int brow = tid >> 5;          // 0..7
    const int bcol = (tid & 31) * 4;    // 0..124

    const float* Ap = A + (size_t)(m0 + arow) * HID + acol;
    const float* Bp = W + (size_t)brow * NKV + n0 + bcol;

    float acc[8][8];
    #pragma unroll
    for (int i = 0; i < 8; i++)
        #pragma unroll
        for (int j = 0; j < 8; j++) acc[i][j] = 0.f;

    // prologue: stage k-tile 0
    float4 av = *(const float4*)(Ap);
    float4 bv = *(const float4*)(Bp);
    As[0][acol + 0][arow] = av.x; As[0][acol + 1][arow] = av.y;
    As[0][acol + 2][arow] = av.z; As[0][acol + 3][arow] = av.w;
    *(float4*)&Bs[0][brow][bcol] = bv;
    __syncthreads();

    int buf = 0;
    const int KT = HID / BK;
    for (int kt = 0; kt < KT; kt++) {
        const bool more = (kt + 1) < KT;
        if (more) {
            av = *(const float4*)(Ap + (kt + 1) * BK);
            bv = *(const float4*)(Bp + (size_t)(kt + 1) * BK * NKV);
        }
        #pragma unroll
        for (int kk = 0; kk < BK; kk++) {
            float a[8], b8[8];
            #pragma unroll
            for (int i = 0; i < 4; i++) {
                a[i]     = As[buf][kk][ty * 4 + i];
                a[4 + i] = As[buf][kk][64 + ty * 4 + i];
            }
            float4 b0 = *(const float4*)&Bs[buf][kk][tx * 4];
            float4 b1 = *(const float4*)&Bs[buf][kk][64 + tx * 4];
            b8[0] = b0.x; b8[1] = b0.y; b8[2] = b0.z; b8[3] = b0.w;
            b8[4] = b1.x; b8[5] = b1.y; b8[6] = b1.z; b8[7] = b1.w;
            #pragma unroll
            for (int i = 0; i < 8; i++)
                #pragma unroll
                for (int j = 0; j < 8; j++)
                    acc[i][j] = fmaf(a[i], b8[j], acc[i][j]);
        }
        if (more) {
            buf ^= 1;
            As[buf][acol + 0][arow] = av.x; As[buf][acol + 1][arow] = av.y;
            As[buf][acol + 2][arow] = av.z; As[buf][acol + 3][arow] = av.w;
            *(float4*)&Bs[buf][brow][bcol] = bv;
            __syncthreads();
        }
    }

    // epilogue: bias + relu, vectorized stores
    #pragma unroll
    for (int i = 0; i < 8; i++) {
        const int r = m0 + ((i < 4) ? (ty * 4 + i) : (64 + ty * 4 + (i - 4)));
        #pragma unroll
        for (int jj = 0; jj < 2; jj++) {
            const int c = n0 + jj * 64 + tx * 4;
            float4 v;
            v.x = fmaxf(acc[i][jj * 4 + 0] + bias[c + 0], 0.f);
            v.y = fmaxf(acc[i][jj * 4 + 1] + bias[c + 1], 0.f);
            v.z = fmaxf(acc[i][jj * 4 + 2] + bias[c + 2], 0.f);
            v.w = fmaxf(acc[i][jj * 4 + 3] + bias[c + 3], 0.f);
            *(float4*)(Cout + (size_t)r * NKV + c) = v;
        }
    }
}

// ---------------------------------------------------------------------------
// dots: valid[m,n] = (sum_hd K1[m, n*64+hd] * RH[n,hd]) > 0.5   (K1 already relu'd)
// one warp per (m,n)
// ---------------------------------------------------------------------------
__global__ void dots_kernel(const float* __restrict__ RH)
{
    const int gw   = blockIdx.x * (blockDim.x >> 5) + (threadIdx.x >> 5);
    const int lane = threadIdx.x & 31;
    const int m = gw >> 4;
    const int n = gw & 15;
    if (m >= MTOT) return;
    const float* kp = g_K1 + (size_t)m * NKV + n * HD;
    const float* rp = RH + n * HD;
    float s = kp[lane] * rp[lane] + kp[lane + 32] * rp[lane + 32];
    #pragma unroll
    for (int o = 16; o; o >>= 1) s += __shfl_xor_sync(0xffffffffu, s, o);
    if (lane == 0) g_valid[m * NH + n] = (s > 0.5f) ? 1 : 0;
}

// ---------------------------------------------------------------------------
// scans: one block per (b, n). Reproduces the reference semantics exactly:
//  forward:  fa[0]=fb[0]=0; for l=1..L-1: if valid[l] { fb=fa; fa=l; }
//  backward: ba[L-1]=bb[L-1]=L-1; for l=L-2..0: if valid[l] { bb=ba; ba=L-1-l; }
// ---------------------------------------------------------------------------
__global__ void scan_kernel()
{
    __shared__ unsigned char sv[LEN];
    __shared__ int2 sf[LEN];
    __shared__ int2 sb[LEN];
    const int b = blockIdx.x >> 4;
    const int n = blockIdx.x & 15;

    for (int l = threadIdx.x; l < LEN; l += blockDim.x)
        sv[l] = g_valid[(size_t)(b * LEN + l) * NH + n];
    __syncthreads();

    if (threadIdx.x == 0) {
        int a = 0, bb = 0;
        sf[0] = make_int2(0, 0);
        for (int l = 1; l < LEN; l++) {
            if (sv[l]) { bb = a; a = l; }
            sf[l] = make_int2(a, bb);
        }
    } else if (threadIdx.x == 32) {
        int a = LEN - 1, bb = LEN - 1;
        sb[LEN - 1] = make_int2(LEN - 1, LEN - 1);
        for (int l = LEN - 2; l >= 0; l--) {
            if (sv[l]) { bb = a; a = (LEN - 1) - l; }
            sb[l] = make_int2(a, bb);
        }
    }
    __syncthreads();

    for (int l = threadIdx.x; l < LEN; l += blockDim.x) {
        const size_t o = (size_t)(b * LEN + l) * NH + n;
        g_fm[o] = sf[l];
        g_bm[o] = sb[l];
    }
}

// ---------------------------------------------------------------------------
// gather: out[m, n*64+h] = w0*V[fa] + w1*V[fb] + w2*V[ba] + w3*V[bb]
// thread per (m, n, h/4), float4 everywhere.
// ---------------------------------------------------------------------------
__global__ void gather_kernel(const float* __restrict__ bw, float* __restrict__ out)
{
    const int t = blockIdx.x * blockDim.x + threadIdx.x;
    const int h4 = t & 15;
    const int n  = (t >> 4) & 15;
    const int m  = t >> 8;
    if (m >= MTOT) return;
    const int b = m >> 11;          // m / LEN
    const size_t io = (size_t)m * NH + n;
    const int2 f  = g_fm[io];
    const int2 bk = g_bm[io];
    const float4 w = *(const float4*)(bw + n * 4);
    const int base = b * LEN;
    const int col = n * HD + h4 * 4;
    const float4 v0 = *(const float4*)(g_V1 + (size_t)(base + f.x)  * NKV + col);
    const float4 v1 = *(const float4*)(g_V1 + (size_t)(base + f.y)  * NKV + col);
    const float4 v2 = *(const float4*)(g_V1 + (size_t)(base + bk.x) * NKV + col);
    const float4 v3 = *(const float4*)(g_V1 + (size_t)(base + bk.y) * NKV + col);
    float4 r;
    r.x = w.x * v0.x + w.y * v1.x + w.z * v2.x + w.w * v3.x;
    r.y = w.x * v0.y + w.y * v1.y + w.z * v2.y + w.w * v3.y;
    r.z = w.x * v0.z + w.y * v1.z + w.z * v2.z + w.w * v3.z;
    r.w = w.x * v0.w + w.y * v1.w + w.z * v2.w + w.w * v3.w;
    *(float4*)(out + (size_t)m * NKV + col) = r;
}

// ---------------------------------------------------------------------------
extern "C" void kernel_launch(void* const* d_in, const int* in_sizes, int n_in,
                              void* d_out, int out_size)
{
    const float* hs  = (const float*)d_in[0];  // hidden_states [8,2048,1024]
    const float* K1w = (const float*)d_in[1];  // [1024,1024]
    const float* K1b = (const float*)d_in[2];  // [1024]
    const float* V1w = (const float*)d_in[3];  // [1024,1024]
    const float* V1b = (const float*)d_in[4];  // [1024]
    const float* bw  = (const float*)d_in[5];  // [1,1,16,1,4]
    const float* RH  = (const float*)d_in[6];  // [16,64]
    float* out = (float*)d_out;

    dim3 gg(16, MTOT / BM);
    gemm_relu_kernel<<<gg, 256>>>(hs, V1w, V1b, K1w, K1b);

    // 262144 (m,n) warps, 8 warps per block
    dots_kernel<<<(MTOT * NH) / 8, 256>>>(RH);

    scan_kernel<<<BSZ * NH, 128>>>();

    const int nthreads = MTOT * NH * (HD / 4);
    gather_kernel<<<(nthreads + 255) / 256, 256>>>(bw, out);
}

// round 3
// speedup vs baseline: 1.5850x; 1.5850x over previous
#include <cuda_runtime.h>
#include <cuda_bf16.h>

#define BSZ 8
#define LEN 2048
#define HID 1024
#define NH  16
#define HD  64
#define MTOT (BSZ*LEN)      /* 16384 */
#define NKV  (NH*HD)        /* 1024  */
#define MARGIN 4e-3f

#define BM 256
#define BN 128
#define BK 64
#define NSEG 3
#define KITER (HID/BK)          /* 16 */
#define NITER (NSEG*KITER)      /* 48 */

// ---------------- scratch (device globals; allocation-free rule) ------------
__device__ float g_V1[(size_t)MTOT * NKV];
__device__ __nv_bfloat16 g_Ahi[(size_t)MTOT * HID];
__device__ __nv_bfloat16 g_Amid[(size_t)MTOT * HID];
__device__ __nv_bfloat16 g_WhiV[(size_t)NKV * HID];   // [n][k] K-major
__device__ __nv_bfloat16 g_WmidV[(size_t)NKV * HID];
__device__ __nv_bfloat16 g_WhiK[(size_t)NKV * HID];
__device__ __nv_bfloat16 g_WmidK[(size_t)NKV * HID];
__device__ unsigned char g_valid[MTOT * NH];
__device__ int2 g_fm[MTOT * NH];
__device__ int2 g_bm[MTOT * NH];
__device__ int g_fixcnt;
__device__ int g_fixlist[MTOT * NH];

#define SWZ(x) ((x) ^ (((x) >> 3) & 0x70))

__device__ __forceinline__ unsigned smem_u32(const void* p) {
    unsigned a;
    asm("{ .reg .u64 t; cvta.to.shared.u64 t, %1; cvt.u32.u64 %0, t; }" : "=r"(a) : "l"(p));
    return a;
}
#define LDSM_X4(r0, r1, r2, r3, addr) \
    asm volatile("ldmatrix.sync.aligned.m8n8.x4.shared.b16 {%0,%1,%2,%3},[%4];" \
        : "=r"(r0), "=r"(r1), "=r"(r2), "=r"(r3) : "r"(addr))
#define MMA16816(c, a0, a1, a2, a3, b0, b1) \
    asm volatile("mma.sync.aligned.m16n8k16.row.col.f32.bf16.bf16.f32 " \
        "{%0,%1,%2,%3},{%4,%5,%6,%7},{%8,%9},{%0,%1,%2,%3};" \
        : "+f"((c)[0]), "+f"((c)[1]), "+f"((c)[2]), "+f"((c)[3]) \
        : "r"(a0), "r"(a1), "r"(a2), "r"(a3), "r"(b0), "r"(b1))

// ---------------------------------------------------------------------------
__global__ void init_kernel() { if (threadIdx.x == 0) g_fixcnt = 0; }

// split hidden_states -> hi/mid bf16 (each thread: 8 consecutive k)
__global__ void splitA_kernel(const float* __restrict__ hs)
{
    const size_t t = (size_t)blockIdx.x * blockDim.x + threadIdx.x;  // 2M threads
    const size_t o = t * 8;
    float4 x0 = *(const float4*)(hs + o);
    float4 x1 = *(const float4*)(hs + o + 4);
    float xs[8] = {x0.x, x0.y, x0.z, x0.w, x1.x, x1.y, x1.z, x1.w};
    union { __nv_bfloat16 b[8]; uint4 u; } h, md;
    #pragma unroll
    for (int i = 0; i < 8; i++) {
        h.b[i]  = __float2bfloat16(xs[i]);
        md.b[i] = __float2bfloat16(xs[i] - __bfloat162float(h.b[i]));
    }
    *(uint4*)(g_Ahi + o)  = h.u;
    *(uint4*)(g_Amid + o) = md.u;
}

// transpose + split weights: W[k][n] f32 -> out[n][k] bf16 hi/mid
__global__ void splitW_kernel(const float* __restrict__ Wv, const float* __restrict__ Wk)
{
    __shared__ float s[32][33];
    const float* W = blockIdx.z ? Wk : Wv;
    __nv_bfloat16* Ohi  = blockIdx.z ? g_WhiK  : g_WhiV;
    __nv_bfloat16* Omid = blockIdx.z ? g_WmidK : g_WmidV;
    const int kb = blockIdx.x * 32, nb = blockIdx.y * 32;
    const int c = threadIdx.x & 31, r0 = threadIdx.x >> 5;   // 256 threads
    #pragma unroll
    for (int j = 0; j < 4; j++) {
        int r = r0 + j * 8;
        s[r][c] = W[(size_t)(kb + r) * NKV + nb + c];
    }
    __syncthreads();
    #pragma unroll
    for (int j = 0; j < 4; j++) {
        int r = r0 + j * 8;            // n-local
        float x = s[c][r];             // (k-local=c, n-local=r)
        __nv_bfloat16 hb = __float2bfloat16(x);
        Ohi [(size_t)(nb + r) * HID + kb + c] = hb;
        Omid[(size_t)(nb + r) * HID + kb + c] = __float2bfloat16(x - __bfloat162float(hb));
    }
}

// ---------------------------------------------------------------------------
// HMMA GEMM: CTA = 256(m) x 128(n) tile for one path.
//   grid.x 0..7  : V path (write relu(A@Wv+bv))
//   grid.x 8..15 : K path (fused dots + threshold + fixlist)
// 3 split-product segments: (hi,hi), (hi,mid), (mid,hi), accumulated fp32.
// ---------------------------------------------------------------------------
__global__ __launch_bounds__(512, 1)
void mma_kernel(const float* __restrict__ biasV, const float* __restrict__ biasK,
                const float* __restrict__ RH)
{
    __shared__ __align__(1024) unsigned char smem_buf[49152];
    unsigned char* sApt = smem_buf;              // 256*128 = 32KB
    unsigned char* sBpt = smem_buf + 32768;      // 128*128 = 16KB
    const unsigned sAu = smem_u32(sApt);
    const unsigned sBu = smem_u32(sBpt);

    const int tid = threadIdx.x;
    const int lane = tid & 31, wid = tid >> 5;
    const int warpM = wid & 3, warpN = wid >> 2;      // 4x4 warp grid
    const int z  = blockIdx.x >> 3;
    const int n0 = (blockIdx.x & 7) * BN;
    const int m0 = blockIdx.y * BM;

    const __nv_bfloat16* Ahi  = g_Ahi;
    const __nv_bfloat16* Amid = g_Amid;
    const __nv_bfloat16* Whi  = z ? g_WhiK  : g_WhiV;
    const __nv_bfloat16* Wmid = z ? g_WmidK : g_WmidV;

    // global load mapping: c = chunk(16B) 0..7, r0 = row base 0..63
    const int lc = tid & 7;
    const int lr = tid >> 3;

    float acc[4][4][4];
    #pragma unroll
    for (int i = 0; i < 4; i++)
        #pragma unroll
        for (int j = 0; j < 4; j++)
            #pragma unroll
            for (int q = 0; q < 4; q++) acc[i][j][q] = 0.f;

    // ldmatrix address components (per thread)
    const int aRowBase = warpM * 64 + (lane & 15);
    const int bRowBase = warpN * 32 + (lane & 15);
    const int khalf = lane >> 4;   // 0/1 -> k-chunk offset within kstep

    // prefetch iter 0
    uint4 pa[4], pb[2];
    {
        const __nv_bfloat16* aS = Ahi;  // seg 0
        const __nv_bfloat16* bS = Whi;
        #pragma unroll
        for (int j = 0; j < 4; j++)
            pa[j] = *(const uint4*)(aS + (size_t)(m0 + lr + 64 * j) * HID + lc * 8);
        #pragma unroll
        for (int j = 0; j < 2; j++)
            pb[j] = *(const uint4*)(bS + (size_t)(n0 + lr + 64 * j) * HID + lc * 8);
    }

    for (int it = 0; it < NITER; it++) {
        __syncthreads();
        // store staged tile (swizzled)
        #pragma unroll
        for (int j = 0; j < 4; j++) {
            int row = lr + 64 * j;
            *(uint4*)(sApt + SWZ(row * 128 + lc * 16)) = pa[j];
        }
        #pragma unroll
        for (int j = 0; j < 2; j++) {
            int row = lr + 64 * j;
            *(uint4*)(sBpt + SWZ(row * 128 + lc * 16)) = pb[j];
        }
        __syncthreads();

        if (it + 1 < NITER) {
            int nit = it + 1;
            int seg = nit >> 4;
            int kk = (nit & 15) * BK;
            const __nv_bfloat16* aS = (seg == 2) ? Amid : Ahi;
            const __nv_bfloat16* bS = (seg == 1) ? Wmid : Whi;
            #pragma unroll
            for (int j = 0; j < 4; j++)
                pa[j] = *(const uint4*)(aS + (size_t)(m0 + lr + 64 * j) * HID + kk + lc * 8);
            #pragma unroll
            for (int j = 0; j < 2; j++)
                pb[j] = *(const uint4*)(bS + (size_t)(n0 + lr + 64 * j) * HID + kk + lc * 8);
        }

        #pragma unroll
        for (int ks = 0; ks < 4; ks++) {
            unsigned af[4][4], bf[2][4];
            #pragma unroll
            for (int mf = 0; mf < 4; mf++) {
                int row = aRowBase + mf * 16;
                int chunk = ks * 2 + khalf;
                unsigned addr = sAu + row * 128 + ((chunk ^ (row & 7)) << 4);
                LDSM_X4(af[mf][0], af[mf][1], af[mf][2], af[mf][3], addr);
            }
            #pragma unroll
            for (int nb = 0; nb < 2; nb++) {
                int row = bRowBase + nb * 16;
                int chunk = ks * 2 + khalf;
                unsigned addr = sBu + row * 128 + ((chunk ^ (row & 7)) << 4);
                LDSM_X4(bf[nb][0], bf[nb][1], bf[nb][2], bf[nb][3], addr);
            }
            #pragma unroll
            for (int mf = 0; mf < 4; mf++)
                #pragma unroll
                for (int nf = 0; nf < 4; nf++) {
                    unsigned b0 = bf[nf >> 1][(nf & 1) ? 1 : 0];
                    unsigned b1 = bf[nf >> 1][(nf & 1) ? 3 : 2];
                    MMA16816(acc[mf][nf], af[mf][0], af[mf][1], af[mf][2], af[mf][3], b0, b1);
                }
        }
    }

    // ---------------- epilogue ----------------
    const int rBase = m0 + warpM * 64 + (lane >> 2);
    const int cBase = n0 + warpN * 32 + (lane & 3) * 2;

    if (z == 0) {
        #pragma unroll
        for (int mf = 0; mf < 4; mf++) {
            #pragma unroll
            for (int nf = 0; nf < 4; nf++) {
                int col = cBase + nf * 8;
                float b0 = biasV[col], b1 = biasV[col + 1];
                int r0 = rBase + mf * 16;
                float2 v;
                v.x = fmaxf(acc[mf][nf][0] + b0, 0.f);
                v.y = fmaxf(acc[mf][nf][1] + b1, 0.f);
                *(float2*)(g_V1 + (size_t)r0 * NKV + col) = v;
                v.x = fmaxf(acc[mf][nf][2] + b0, 0.f);
                v.y = fmaxf(acc[mf][nf][3] + b1, 0.f);
                *(float2*)(g_V1 + (size_t)(r0 + 8) * NKV + col) = v;
            }
        }
    } else {
        __syncthreads();                       // smem_buf no longer read as tiles
        float* sdots = (float*)smem_buf;       // [256][2]
        if (tid < 512) sdots[tid] = 0.f;
        __syncthreads();
        const int hloc = warpN >> 1;           // head within tile (BN=128 -> 2 heads)
        #pragma unroll
        for (int mf = 0; mf < 4; mf++) {
            float slo = 0.f, shi = 0.f;
            #pragma unroll
            for (int nf = 0; nf < 4; nf++) {
                int col = cBase + nf * 8;
                float b0 = biasK[col], b1 = biasK[col + 1];
                float w0 = RH[col],   w1 = RH[col + 1];
                slo += fmaxf(acc[mf][nf][0] + b0, 0.f) * w0
                     + fmaxf(acc[mf][nf][1] + b1, 0.f) * w1;
                shi += fmaxf(acc[mf][nf][2] + b0, 0.f) * w0
                     + fmaxf(acc[mf][nf][3] + b1, 0.f) * w1;
            }
            slo += __shfl_xor_sync(0xffffffffu, slo, 1);
            slo += __shfl_xor_sync(0xffffffffu, slo, 2);
            shi += __shfl_xor_sync(0xffffffffu, shi, 1);
            shi += __shfl_xor_sync(0xffffffffu, shi, 2);
            if ((lane & 3) == 0) {
                int rloc = warpM * 64 + mf * 16 + (lane >> 2);
                atomicAdd(&sdots[rloc * 2 + hloc], slo);
                atomicAdd(&sdots[(rloc + 8) * 2 + hloc], shi);
            }
        }
        __syncthreads();
        if (tid < 512) {
            int rloc = tid >> 1, h = tid & 1;
            int m = m0 + rloc;
            int n = (n0 >> 6) + h;
            float dd = sdots[tid];
            int o = m * NH + n;
            if (fabsf(dd - 0.5f) < MARGIN) {
                int ix = atomicAdd(&g_fixcnt, 1);
                g_fixlist[ix] = (m << 4) | n;
                g_valid[o] = 0;   // placeholder; fix_kernel overwrites
            } else {
                g_valid[o] = (dd > 0.5f) ? 1 : 0;
            }
        }
    }
}

// ---------------------------------------------------------------------------
// exact fp32 recompute of dots for entries near the 0.5 threshold
// ---------------------------------------------------------------------------
__global__ void fix_kernel(const float* __restrict__ hs, const float* __restrict__ K1w,
                           const float* __restrict__ K1b, const float* __restrict__ RH)
{
    __shared__ float sred[64];
    const int cnt = g_fixcnt;
    const int col = threadIdx.x >> 2;   // 0..63
    const int q   = threadIdx.x & 3;
    for (int i = blockIdx.x; i < cnt; i += gridDim.x) {
        int mn = g_fixlist[i];
        int m = mn >> 4, n = mn & 15;
        const float* a = hs + (size_t)m * HID;
        const float* w = K1w + n * HD + col;
        float acc = 0.f;
        for (int k = q * 256; k < q * 256 + 256; k++)
            acc = fmaf(a[k], w[(size_t)k * NKV], acc);
        acc += __shfl_xor_sync(0xffffffffu, acc, 1);
        acc += __shfl_xor_sync(0xffffffffu, acc, 2);
        if (q == 0)
            sred[col] = fmaxf(acc + K1b[n * HD + col], 0.f) * RH[n * HD + col];
        __syncthreads();
        if (threadIdx.x == 0) {
            float d = 0.f;
            for (int c = 0; c < 64; c++) d += sred[c];
            g_valid[m * NH + n] = (d > 0.5f) ? 1 : 0;
        }
        __syncthreads();
    }
}

// ---------------------------------------------------------------------------
__global__ void scan_kernel()
{
    __shared__ unsigned char sv[LEN];
    __shared__ int2 sf[LEN];
    __shared__ int2 sb[LEN];
    const int b = blockIdx.x >> 4;
    const int n = blockIdx.x & 15;

    for (int l = threadIdx.x; l < LEN; l += blockDim.x)
        sv[l] = g_valid[(size_t)(b * LEN + l) * NH + n];
    __syncthreads();

    if (threadIdx.x == 0) {
        int a = 0, bb = 0;
        sf[0] = make_int2(0, 0);
        for (int l = 1; l < LEN; l++) {
            if (sv[l]) { bb = a; a = l; }
            sf[l] = make_int2(a, bb);
        }
    } else if (threadIdx.x == 32) {
        int a = LEN - 1, bb = LEN - 1;
        sb[LEN - 1] = make_int2(LEN - 1, LEN - 1);
        for (int l = LEN - 2; l >= 0; l--) {
            if (sv[l]) { bb = a; a = (LEN - 1) - l; }
            sb[l] = make_int2(a, bb);
        }
    }
    __syncthreads();

    for (int l = threadIdx.x; l < LEN; l += blockDim.x) {
        const size_t o = (size_t)(b * LEN + l) * NH + n;
        g_fm[o] = sf[l];
        g_bm[o] = sb[l];
    }
}

// ---------------------------------------------------------------------------
__global__ void gather_kernel(const float* __restrict__ bw, float* __restrict__ out)
{
    const int t = blockIdx.x * blockDim.x + threadIdx.x;
    const int h4 = t & 15;
    const int n  = (t >> 4) & 15;
    const int m  = t >> 8;
    if (m >= MTOT) return;
    const int b = m >> 11;
    const size_t io = (size_t)m * NH + n;
    const int2 f  = g_fm[io];
    const int2 bk = g_bm[io];
    const float4 w = *(const float4*)(bw + n * 4);
    const int base = b * LEN;
    const int col = n * HD + h4 * 4;
    const float4 v0 = *(const float4*)(g_V1 + (size_t)(base + f.x)  * NKV + col);
    const float4 v1 = *(const float4*)(g_V1 + (size_t)(base + f.y)  * NKV + col);
    const float4 v2 = *(const float4*)(g_V1 + (size_t)(base + bk.x) * NKV + col);
    const float4 v3 = *(const float4*)(g_V1 + (size_t)(base + bk.y) * NKV + col);
    float4 rr;
    rr.x = w.x * v0.x + w.y * v1.x + w.z * v2.x + w.w * v3.x;
    rr.y = w.x * v0.y + w.y * v1.y + w.z * v2.y + w.w * v3.y;
    rr.z = w.x * v0.z + w.y * v1.z + w.z * v2.z + w.w * v3.z;
    rr.w = w.x * v0.w + w.y * v1.w + w.z * v2.w + w.w * v3.w;
    *(float4*)(out + (size_t)m * NKV + col) = rr;
}

// ---------------------------------------------------------------------------
extern "C" void kernel_launch(void* const* d_in, const int* in_sizes, int n_in,
                              void* d_out, int out_size)
{
    const float* hs  = (const float*)d_in[0];
    const float* K1w = (const float*)d_in[1];
    const float* K1b = (const float*)d_in[2];
    const float* V1w = (const float*)d_in[3];
    const float* V1b = (const float*)d_in[4];
    const float* bw  = (const float*)d_in[5];
    const float* RH  = (const float*)d_in[6];
    float* out = (float*)d_out;

    init_kernel<<<1, 32>>>();
    splitA_kernel<<<(MTOT * HID / 8) / 256, 256>>>(hs);
    splitW_kernel<<<dim3(32, 32, 2), 256>>>(V1w, K1w);
    mma_kernel<<<dim3(16, MTOT / BM), 512>>>(V1b, K1b, RH);
    fix_kernel<<<256, 256>>>(hs, K1w, K1b, RH);
    scan_kernel<<<BSZ * NH, 128>>>();
    gather_kernel<<<(MTOT * NH * 16) / 256, 256>>>(bw, out);
}